// round 1
// baseline (speedup 1.0000x reference)
#include <cuda_runtime.h>
#include <math.h>

#define N_NODES 50000
#define N_EDGES 800000
#define F_DIM   128
#define F4      32      // float4 per feature row
#define HID     256
#define NCLS    40

// ---------------- device scratch (static: no allocation allowed) ----------------
__device__ int    g_deg[N_NODES];
__device__ int    g_rowstart[N_NODES + 1];
__device__ int    g_cursor[N_NODES];
__device__ float  g_norm[N_NODES];
__device__ int    g_csr_src[N_EDGES];
__device__ float  g_csr_w[N_EDGES];
__device__ float4 g_x0[N_NODES * F4];
__device__ float4 g_x1[N_NODES * F4];
__device__ float4 g_y [N_NODES * F4];
__device__ float4 g_h [N_NODES * (HID / 4)];

// ---------------- build: degree ----------------
__global__ void zero_deg_kernel() {
    int i = blockIdx.x * blockDim.x + threadIdx.x;
    if (i < N_NODES) g_deg[i] = 0;
}

__global__ void deg_kernel(const int* __restrict__ dst) {
    int i = blockIdx.x * blockDim.x + threadIdx.x;
    if (i < N_EDGES) atomicAdd(&g_deg[dst[i]], 1);
}

__global__ void norm_kernel() {
    int i = blockIdx.x * blockDim.x + threadIdx.x;
    if (i < N_NODES) {
        int d = g_deg[i];
        g_norm[i] = rsqrtf((float)(d < 1 ? 1 : d));
    }
}

// single-block exclusive prefix scan over degrees -> rowstart + cursor
__global__ void scan_kernel() {
    __shared__ int part[1024];
    const int CH = (N_NODES + 1023) / 1024;   // 49
    int t  = threadIdx.x;
    int st = t * CH;
    int en = st + CH; if (en > N_NODES) en = N_NODES;
    if (st > N_NODES) st = N_NODES;

    int s = 0;
    for (int i = st; i < en; i++) s += g_deg[i];
    part[t] = s;
    __syncthreads();
    // Hillis-Steele inclusive scan
    for (int off = 1; off < 1024; off <<= 1) {
        int v = (t >= off) ? part[t - off] : 0;
        __syncthreads();
        part[t] += v;
        __syncthreads();
    }
    int off = part[t] - s;   // exclusive prefix for this chunk
    for (int i = st; i < en; i++) {
        g_rowstart[i] = off;
        g_cursor[i]   = off;
        off += g_deg[i];
    }
    if (t == 1023) g_rowstart[N_NODES] = off;   // == N_EDGES
}

// fill CSR: csr_src = src, csr_w = norm[src]  (norm[dst] applied at use site)
__global__ void fill_kernel(const int* __restrict__ src, const int* __restrict__ dst) {
    int i = blockIdx.x * blockDim.x + threadIdx.x;
    if (i < N_EDGES) {
        int s = src[i];
        int d = dst[i];
        int pos = atomicAdd(&g_cursor[d], 1);
        g_csr_src[pos] = s;
        g_csr_w[pos]   = g_norm[s];
    }
}

// ---------------- init: x0 = features, y = features (DROPOUT = 0) ----------------
__global__ void init_kernel(const float4* __restrict__ feat) {
    int i = blockIdx.x * blockDim.x + threadIdx.x;   // over N_NODES*F4 float4s
    if (i < N_NODES * F4) {
        float4 v = feat[i];
        g_x0[i] = v;
        g_y[i]  = v;
    }
}

// ---------------- propagation: pull over CSR, fused y-accumulate ----------------
// block = 256 threads = 8 nodes x 32 lanes; lane owns 4 feature dims (float4)
__global__ void prop_kernel(int dir) {
    const float4* __restrict__ xin  = dir ? g_x1 : g_x0;
    float4*       __restrict__ xout = dir ? g_x0 : g_x1;

    int node = blockIdx.x * 8 + (threadIdx.x >> 5);
    int lane = threadIdx.x & 31;
    if (node >= N_NODES) return;

    int beg = g_rowstart[node];
    int end = g_rowstart[node + 1];

    float4 acc = make_float4(0.f, 0.f, 0.f, 0.f);
    int e = beg;
    for (; e + 4 <= end; e += 4) {
        int   s0 = __ldg(&g_csr_src[e + 0]);
        int   s1 = __ldg(&g_csr_src[e + 1]);
        int   s2 = __ldg(&g_csr_src[e + 2]);
        int   s3 = __ldg(&g_csr_src[e + 3]);
        float w0 = __ldg(&g_csr_w[e + 0]);
        float w1 = __ldg(&g_csr_w[e + 1]);
        float w2 = __ldg(&g_csr_w[e + 2]);
        float w3 = __ldg(&g_csr_w[e + 3]);
        float4 v0 = __ldg(&xin[s0 * F4 + lane]);
        float4 v1 = __ldg(&xin[s1 * F4 + lane]);
        float4 v2 = __ldg(&xin[s2 * F4 + lane]);
        float4 v3 = __ldg(&xin[s3 * F4 + lane]);
        acc.x = fmaf(v0.x, w0, acc.x); acc.y = fmaf(v0.y, w0, acc.y);
        acc.z = fmaf(v0.z, w0, acc.z); acc.w = fmaf(v0.w, w0, acc.w);
        acc.x = fmaf(v1.x, w1, acc.x); acc.y = fmaf(v1.y, w1, acc.y);
        acc.z = fmaf(v1.z, w1, acc.z); acc.w = fmaf(v1.w, w1, acc.w);
        acc.x = fmaf(v2.x, w2, acc.x); acc.y = fmaf(v2.y, w2, acc.y);
        acc.z = fmaf(v2.z, w2, acc.z); acc.w = fmaf(v2.w, w2, acc.w);
        acc.x = fmaf(v3.x, w3, acc.x); acc.y = fmaf(v3.y, w3, acc.y);
        acc.z = fmaf(v3.z, w3, acc.z); acc.w = fmaf(v3.w, w3, acc.w);
    }
    for (; e < end; e++) {
        int   s = __ldg(&g_csr_src[e]);
        float w = __ldg(&g_csr_w[e]);
        float4 v = __ldg(&xin[s * F4 + lane]);
        acc.x = fmaf(v.x, w, acc.x); acc.y = fmaf(v.y, w, acc.y);
        acc.z = fmaf(v.z, w, acc.z); acc.w = fmaf(v.w, w, acc.w);
    }

    float nd = g_norm[node];
    acc.x *= nd; acc.y *= nd; acc.z *= nd; acc.w *= nd;

    int idx = node * F4 + lane;
    xout[idx] = acc;
    float4 yv = g_y[idx];
    yv.x += acc.x; yv.y += acc.y; yv.z += acc.z; yv.w += acc.w;
    g_y[idx] = yv;
}

// ---------------- GEMM1: h = relu( (y*0.25) @ W1 + b1 )  [50000,128]x[128,256] ----
// BM=64, BN=64, BK=16, 256 threads, 4x4 per thread
__global__ void gemm1_kernel(const float* __restrict__ W1, const float* __restrict__ b1) {
    __shared__ float As[16][68];   // [k][m], padded (272B rows, 16B aligned)
    __shared__ float Bs[16][64];   // [k][n]

    int tid = threadIdx.x;
    int m0 = blockIdx.x * 64;
    int n0 = blockIdx.y * 64;
    int ty = tid >> 4;          // 0..15
    int tx = tid & 15;          // 0..15

    const float* y = (const float*)g_y;

    int arow = tid >> 2;        // 0..63
    int ak   = (tid & 3) * 4;   // 0,4,8,12
    int brow = tid >> 4;        // 0..15
    int bc   = (tid & 15) * 4;  // 0..60

    float acc[4][4];
#pragma unroll
    for (int i = 0; i < 4; i++)
#pragma unroll
        for (int j = 0; j < 4; j++) acc[i][j] = 0.f;

    for (int k0 = 0; k0 < F_DIM; k0 += 16) {
        float4 av = make_float4(0.f, 0.f, 0.f, 0.f);
        int gm = m0 + arow;
        if (gm < N_NODES) av = *(const float4*)&y[gm * F_DIM + k0 + ak];
        As[ak + 0][arow] = av.x * 0.25f;
        As[ak + 1][arow] = av.y * 0.25f;
        As[ak + 2][arow] = av.z * 0.25f;
        As[ak + 3][arow] = av.w * 0.25f;

        float4 bv = *(const float4*)&W1[(k0 + brow) * HID + n0 + bc];
        *(float4*)&Bs[brow][bc] = bv;

        __syncthreads();
#pragma unroll
        for (int kk = 0; kk < 16; kk++) {
            float4 a4 = *(const float4*)&As[kk][ty * 4];
            float4 b4 = *(const float4*)&Bs[kk][tx * 4];
            float a_[4] = {a4.x, a4.y, a4.z, a4.w};
            float b_[4] = {b4.x, b4.y, b4.z, b4.w};
#pragma unroll
            for (int i = 0; i < 4; i++)
#pragma unroll
                for (int j = 0; j < 4; j++)
                    acc[i][j] = fmaf(a_[i], b_[j], acc[i][j]);
        }
        __syncthreads();
    }

    float4 bias = *(const float4*)&b1[n0 + tx * 4];
    float* h = (float*)g_h;
#pragma unroll
    for (int i = 0; i < 4; i++) {
        int gm = m0 + ty * 4 + i;
        if (gm < N_NODES) {
            float4 o;
            o.x = fmaxf(acc[i][0] + bias.x, 0.f);
            o.y = fmaxf(acc[i][1] + bias.y, 0.f);
            o.z = fmaxf(acc[i][2] + bias.z, 0.f);
            o.w = fmaxf(acc[i][3] + bias.w, 0.f);
            *(float4*)&h[gm * HID + n0 + tx * 4] = o;
        }
    }
}

// ---------------- GEMM2 + log_softmax fused: out = logsoftmax(h @ W2 + b2) -------
// 32 rows/block, 320 threads (32 rows x 10 class-groups of 4), K chunked by 32
__global__ void gemm2_kernel(const float* __restrict__ W2, const float* __restrict__ b2,
                             float* __restrict__ out) {
    __shared__ float w2c[32][44];   // [k][c] chunk, padded (176B rows, 16B aligned)
    __shared__ float hc[32][33];    // [row][k] chunk
    __shared__ float lg[32][41];    // logits
    __shared__ float rm[32], rs[32];

    int tid = threadIdx.x;          // 0..319
    int r = tid / 10;               // 0..31
    int g = tid % 10;               // 0..9  -> classes 4g..4g+3
    int m0 = blockIdx.x * 32;

    const float* h = (const float*)g_h;

    float a0 = 0.f, a1 = 0.f, a2 = 0.f, a3 = 0.f;

    for (int kb = 0; kb < HID; kb += 32) {
        // stage h chunk: 32 rows x 32 k
        for (int idx = tid; idx < 32 * 32; idx += 320) {
            int rr = idx >> 5, kk = idx & 31;
            int row = m0 + rr;
            hc[rr][kk] = (row < N_NODES) ? h[row * HID + kb + kk] : 0.f;
        }
        // stage W2 chunk: 32 k x 40 c
        for (int idx = tid; idx < 32 * 40; idx += 320) {
            int kk = idx / 40, cc = idx % 40;
            w2c[kk][cc] = W2[(kb + kk) * NCLS + cc];
        }
        __syncthreads();
#pragma unroll
        for (int kk = 0; kk < 32; kk++) {
            float hv = hc[r][kk];
            float4 wv = *(const float4*)&w2c[kk][g * 4];
            a0 = fmaf(hv, wv.x, a0);
            a1 = fmaf(hv, wv.y, a1);
            a2 = fmaf(hv, wv.z, a2);
            a3 = fmaf(hv, wv.w, a3);
        }
        __syncthreads();
    }

    lg[r][g * 4 + 0] = a0 + b2[g * 4 + 0];
    lg[r][g * 4 + 1] = a1 + b2[g * 4 + 1];
    lg[r][g * 4 + 2] = a2 + b2[g * 4 + 2];
    lg[r][g * 4 + 3] = a3 + b2[g * 4 + 3];
    __syncthreads();

    if (tid < 32) {
        float m = -1e30f;
#pragma unroll
        for (int c = 0; c < NCLS; c++) m = fmaxf(m, lg[tid][c]);
        float s = 0.f;
#pragma unroll
        for (int c = 0; c < NCLS; c++) s += expf(lg[tid][c] - m);
        rm[tid] = m;
        rs[tid] = logf(s);
    }
    __syncthreads();

    int row = m0 + r;
    if (row < N_NODES) {
        float sub = rm[r] + rs[r];
        out[row * NCLS + g * 4 + 0] = lg[r][g * 4 + 0] - sub;
        out[row * NCLS + g * 4 + 1] = lg[r][g * 4 + 1] - sub;
        out[row * NCLS + g * 4 + 2] = lg[r][g * 4 + 2] - sub;
        out[row * NCLS + g * 4 + 3] = lg[r][g * 4 + 3] - sub;
    }
}

// ---------------- launch ----------------
extern "C" void kernel_launch(void* const* d_in, const int* in_sizes, int n_in,
                              void* d_out, int out_size) {
    const float* features = (const float*)d_in[0];
    const int*   src      = (const int*)d_in[1];
    const int*   dst      = (const int*)d_in[2];
    const float* W1       = (const float*)d_in[3];
    const float* b1       = (const float*)d_in[4];
    const float* W2       = (const float*)d_in[5];
    const float* b2       = (const float*)d_in[6];
    float*       out      = (float*)d_out;

    const int NB  = (N_NODES + 255) / 256;      // 196
    const int EB  = (N_EDGES + 255) / 256;      // 3125
    const int IB  = (N_NODES * F4 + 255) / 256; // 6250
    const int PB  = (N_NODES + 7) / 8;          // 6250

    zero_deg_kernel<<<NB, 256>>>();
    deg_kernel<<<EB, 256>>>(dst);
    norm_kernel<<<NB, 256>>>();
    scan_kernel<<<1, 1024>>>();
    fill_kernel<<<EB, 256>>>(src, dst);
    init_kernel<<<IB, 256>>>((const float4*)features);

    prop_kernel<<<PB, 256>>>(0);   // x0 -> x1
    prop_kernel<<<PB, 256>>>(1);   // x1 -> x0
    prop_kernel<<<PB, 256>>>(0);   // x0 -> x1

    dim3 g1((N_NODES + 63) / 64, HID / 64);     // (782, 4)
    gemm1_kernel<<<g1, 256>>>(W1, b1);

    const int G2B = (N_NODES + 31) / 32;        // 1563
    gemm2_kernel<<<G2B, 320>>>(W2, b2, out);
}

// round 2
// speedup vs baseline: 1.2311x; 1.2311x over previous
#include <cuda_runtime.h>
#include <math.h>

#define N_NODES 50000
#define N_EDGES 800000
#define F_DIM   128
#define F4      32      // float4 per feature row
#define HID     256
#define NCLS    40

#define SCAN_BLOCKS ((N_NODES + 255) / 256)   // 196

// ---------------- device scratch (static: no allocation allowed) ----------------
__device__ int    g_deg[N_NODES];
__device__ int    g_rowstart[N_NODES + 1];
__device__ int    g_cursor[N_NODES];
__device__ int    g_bsum[SCAN_BLOCKS];
__device__ int    g_boff[SCAN_BLOCKS];
__device__ float  g_norm[N_NODES];
__device__ int    g_csr_src[N_EDGES];
__device__ float  g_csr_w[N_EDGES];
__device__ float4 g_x0[N_NODES * F4];
__device__ float4 g_x1[N_NODES * F4];
__device__ float4 g_y [N_NODES * F4];
__device__ float4 g_h [N_NODES * (HID / 4)];

// ---------------- build: degree ----------------
__global__ void zero_deg_kernel() {
    int i = blockIdx.x * blockDim.x + threadIdx.x;
    if (i < N_NODES) g_deg[i] = 0;
}

__global__ void deg_kernel(const int* __restrict__ dst) {
    int i = blockIdx.x * blockDim.x + threadIdx.x;
    if (i < N_EDGES) atomicAdd(&g_deg[dst[i]], 1);
}

__global__ void norm_kernel() {
    int i = blockIdx.x * blockDim.x + threadIdx.x;
    if (i < N_NODES) {
        int d = g_deg[i];
        g_norm[i] = rsqrtf((float)(d < 1 ? 1 : d));
    }
}

// ---------------- hierarchical scan ----------------
__device__ __forceinline__ int warp_incl_scan(int v, int lane) {
#pragma unroll
    for (int o = 1; o < 32; o <<= 1) {
        int n = __shfl_up_sync(0xffffffffu, v, o);
        if (lane >= o) v += n;
    }
    return v;
}

__device__ __forceinline__ int block_incl_scan_256(int v, int tid) {
    __shared__ int ws[8];
    int lane = tid & 31, w = tid >> 5;
    int incl = warp_incl_scan(v, lane);
    if (lane == 31) ws[w] = incl;
    __syncthreads();
    if (w == 0) {
        int s = (lane < 8) ? ws[lane] : 0;
        s = warp_incl_scan(s, lane);
        if (lane < 8) ws[lane] = s;
    }
    __syncthreads();
    if (w > 0) incl += ws[w - 1];
    return incl;
}

// phase 1: block-local exclusive scan into g_rowstart, block totals into g_bsum
__global__ void scan1_kernel() {
    int tid = threadIdx.x;
    int i = blockIdx.x * 256 + tid;
    int v = (i < N_NODES) ? g_deg[i] : 0;
    int incl = block_incl_scan_256(v, tid);
    if (i < N_NODES) g_rowstart[i] = incl - v;     // block-local exclusive
    if (tid == 255) g_bsum[blockIdx.x] = incl;     // block total
}

// phase 2: single-block exclusive scan over the 196 block sums
__global__ void scan2_kernel() {
    int tid = threadIdx.x;
    int v = (tid < SCAN_BLOCKS) ? g_bsum[tid] : 0;
    int incl = block_incl_scan_256(v, tid);
    if (tid < SCAN_BLOCKS) g_boff[tid] = incl - v;
}

// phase 3: add block offsets; also init cursor and terminator
__global__ void scan3_kernel() {
    int i = blockIdx.x * 256 + threadIdx.x;
    if (i < N_NODES) {
        int r = g_rowstart[i] + g_boff[blockIdx.x];
        g_rowstart[i] = r;
        g_cursor[i]   = r;
    }
    if (i == 0) g_rowstart[N_NODES] = N_EDGES;
}

// fill CSR: csr_src = src, csr_w = norm[src]  (norm[dst] applied at use site)
__global__ void fill_kernel(const int* __restrict__ src, const int* __restrict__ dst) {
    int i = blockIdx.x * blockDim.x + threadIdx.x;
    if (i < N_EDGES) {
        int s = src[i];
        int d = dst[i];
        int pos = atomicAdd(&g_cursor[d], 1);
        g_csr_src[pos] = s;
        g_csr_w[pos]   = g_norm[s];
    }
}

// ---------------- init: x0 = features, y = features (DROPOUT = 0) ----------------
__global__ void init_kernel(const float4* __restrict__ feat) {
    int i = blockIdx.x * blockDim.x + threadIdx.x;
    if (i < N_NODES * F4) {
        float4 v = feat[i];
        g_x0[i] = v;
        g_y[i]  = v;
    }
}

// ---------------- propagation: pull over CSR, fused y-accumulate ----------------
// block = 256 threads = 8 nodes x 32 lanes; lane owns 4 feature dims (float4)
__global__ void prop_kernel(int dir) {
    const float4* __restrict__ xin  = dir ? g_x1 : g_x0;
    float4*       __restrict__ xout = dir ? g_x0 : g_x1;

    int node = blockIdx.x * 8 + (threadIdx.x >> 5);
    int lane = threadIdx.x & 31;
    if (node >= N_NODES) return;

    int beg = g_rowstart[node];
    int end = g_rowstart[node + 1];

    float4 acc = make_float4(0.f, 0.f, 0.f, 0.f);
    int e = beg;
    for (; e + 4 <= end; e += 4) {
        int   s0 = __ldg(&g_csr_src[e + 0]);
        int   s1 = __ldg(&g_csr_src[e + 1]);
        int   s2 = __ldg(&g_csr_src[e + 2]);
        int   s3 = __ldg(&g_csr_src[e + 3]);
        float w0 = __ldg(&g_csr_w[e + 0]);
        float w1 = __ldg(&g_csr_w[e + 1]);
        float w2 = __ldg(&g_csr_w[e + 2]);
        float w3 = __ldg(&g_csr_w[e + 3]);
        float4 v0 = __ldg(&xin[s0 * F4 + lane]);
        float4 v1 = __ldg(&xin[s1 * F4 + lane]);
        float4 v2 = __ldg(&xin[s2 * F4 + lane]);
        float4 v3 = __ldg(&xin[s3 * F4 + lane]);
        acc.x = fmaf(v0.x, w0, acc.x); acc.y = fmaf(v0.y, w0, acc.y);
        acc.z = fmaf(v0.z, w0, acc.z); acc.w = fmaf(v0.w, w0, acc.w);
        acc.x = fmaf(v1.x, w1, acc.x); acc.y = fmaf(v1.y, w1, acc.y);
        acc.z = fmaf(v1.z, w1, acc.z); acc.w = fmaf(v1.w, w1, acc.w);
        acc.x = fmaf(v2.x, w2, acc.x); acc.y = fmaf(v2.y, w2, acc.y);
        acc.z = fmaf(v2.z, w2, acc.z); acc.w = fmaf(v2.w, w2, acc.w);
        acc.x = fmaf(v3.x, w3, acc.x); acc.y = fmaf(v3.y, w3, acc.y);
        acc.z = fmaf(v3.z, w3, acc.z); acc.w = fmaf(v3.w, w3, acc.w);
    }
    for (; e < end; e++) {
        int   s = __ldg(&g_csr_src[e]);
        float w = __ldg(&g_csr_w[e]);
        float4 v = __ldg(&xin[s * F4 + lane]);
        acc.x = fmaf(v.x, w, acc.x); acc.y = fmaf(v.y, w, acc.y);
        acc.z = fmaf(v.z, w, acc.z); acc.w = fmaf(v.w, w, acc.w);
    }

    float nd = g_norm[node];
    acc.x *= nd; acc.y *= nd; acc.z *= nd; acc.w *= nd;

    int idx = node * F4 + lane;
    xout[idx] = acc;
    float4 yv = g_y[idx];
    yv.x += acc.x; yv.y += acc.y; yv.z += acc.z; yv.w += acc.w;
    g_y[idx] = yv;
}

// ---------------- GEMM1: h = relu( (y*0.25) @ W1 + b1 )  [50000,128]x[128,256] ----
// BM=128, BN=64, BK=16, 256 threads, 8x4 per thread
__global__ void gemm1_kernel(const float* __restrict__ W1, const float* __restrict__ b1) {
    __shared__ float As[16][132];   // [k][m], padded
    __shared__ float Bs[16][64];    // [k][n]

    int tid = threadIdx.x;
    int m0 = blockIdx.x * 128;
    int n0 = blockIdx.y * 64;
    int ty = tid >> 4;          // 0..15 -> 8 rows each
    int tx = tid & 15;          // 0..15 -> 4 cols each

    const float* y = (const float*)g_y;

    // A staging: thread loads 2 float4 from row (tid>>1), k-offsets (tid&1)*8 +{0,4}
    int arow = tid >> 1;            // 0..127
    int ak   = (tid & 1) * 8;       // 0 or 8
    // B staging: 1 float4 per thread
    int brow = tid >> 4;            // 0..15
    int bc   = (tid & 15) * 4;      // 0..60

    float acc[8][4];
#pragma unroll
    for (int i = 0; i < 8; i++)
#pragma unroll
        for (int j = 0; j < 4; j++) acc[i][j] = 0.f;

    for (int k0 = 0; k0 < F_DIM; k0 += 16) {
        int gm = m0 + arow;
        float4 av0 = make_float4(0.f, 0.f, 0.f, 0.f);
        float4 av1 = make_float4(0.f, 0.f, 0.f, 0.f);
        if (gm < N_NODES) {
            av0 = *(const float4*)&y[gm * F_DIM + k0 + ak];
            av1 = *(const float4*)&y[gm * F_DIM + k0 + ak + 4];
        }
        As[ak + 0][arow] = av0.x * 0.25f;
        As[ak + 1][arow] = av0.y * 0.25f;
        As[ak + 2][arow] = av0.z * 0.25f;
        As[ak + 3][arow] = av0.w * 0.25f;
        As[ak + 4][arow] = av1.x * 0.25f;
        As[ak + 5][arow] = av1.y * 0.25f;
        As[ak + 6][arow] = av1.z * 0.25f;
        As[ak + 7][arow] = av1.w * 0.25f;

        float4 bv = *(const float4*)&W1[(k0 + brow) * HID + n0 + bc];
        *(float4*)&Bs[brow][bc] = bv;

        __syncthreads();
#pragma unroll
        for (int kk = 0; kk < 16; kk++) {
            float4 a0 = *(const float4*)&As[kk][ty * 8];
            float4 a1 = *(const float4*)&As[kk][ty * 8 + 4];
            float4 b4 = *(const float4*)&Bs[kk][tx * 4];
            float a_[8] = {a0.x, a0.y, a0.z, a0.w, a1.x, a1.y, a1.z, a1.w};
            float b_[4] = {b4.x, b4.y, b4.z, b4.w};
#pragma unroll
            for (int i = 0; i < 8; i++)
#pragma unroll
                for (int j = 0; j < 4; j++)
                    acc[i][j] = fmaf(a_[i], b_[j], acc[i][j]);
        }
        __syncthreads();
    }

    float4 bias = *(const float4*)&b1[n0 + tx * 4];
    float* h = (float*)g_h;
#pragma unroll
    for (int i = 0; i < 8; i++) {
        int gm = m0 + ty * 8 + i;
        if (gm < N_NODES) {
            float4 o;
            o.x = fmaxf(acc[i][0] + bias.x, 0.f);
            o.y = fmaxf(acc[i][1] + bias.y, 0.f);
            o.z = fmaxf(acc[i][2] + bias.z, 0.f);
            o.w = fmaxf(acc[i][3] + bias.w, 0.f);
            *(float4*)&h[gm * HID + n0 + tx * 4] = o;
        }
    }
}

// ---------------- GEMM2 + log_softmax fused: out = logsoftmax(h @ W2 + b2) -------
__global__ void gemm2_kernel(const float* __restrict__ W2, const float* __restrict__ b2,
                             float* __restrict__ out) {
    __shared__ float w2c[32][44];
    __shared__ float hc[32][33];
    __shared__ float lg[32][41];
    __shared__ float rm[32], rs[32];

    int tid = threadIdx.x;          // 0..319
    int r = tid / 10;               // 0..31
    int g = tid % 10;               // 0..9  -> classes 4g..4g+3
    int m0 = blockIdx.x * 32;

    const float* h = (const float*)g_h;

    float a0 = 0.f, a1 = 0.f, a2 = 0.f, a3 = 0.f;

    for (int kb = 0; kb < HID; kb += 32) {
        for (int idx = tid; idx < 32 * 32; idx += 320) {
            int rr = idx >> 5, kk = idx & 31;
            int row = m0 + rr;
            hc[rr][kk] = (row < N_NODES) ? h[row * HID + kb + kk] : 0.f;
        }
        for (int idx = tid; idx < 32 * 40; idx += 320) {
            int kk = idx / 40, cc = idx % 40;
            w2c[kk][cc] = W2[(kb + kk) * NCLS + cc];
        }
        __syncthreads();
#pragma unroll
        for (int kk = 0; kk < 32; kk++) {
            float hv = hc[r][kk];
            float4 wv = *(const float4*)&w2c[kk][g * 4];
            a0 = fmaf(hv, wv.x, a0);
            a1 = fmaf(hv, wv.y, a1);
            a2 = fmaf(hv, wv.z, a2);
            a3 = fmaf(hv, wv.w, a3);
        }
        __syncthreads();
    }

    lg[r][g * 4 + 0] = a0 + b2[g * 4 + 0];
    lg[r][g * 4 + 1] = a1 + b2[g * 4 + 1];
    lg[r][g * 4 + 2] = a2 + b2[g * 4 + 2];
    lg[r][g * 4 + 3] = a3 + b2[g * 4 + 3];
    __syncthreads();

    if (tid < 32) {
        float m = -1e30f;
#pragma unroll
        for (int c = 0; c < NCLS; c++) m = fmaxf(m, lg[tid][c]);
        float s = 0.f;
#pragma unroll
        for (int c = 0; c < NCLS; c++) s += expf(lg[tid][c] - m);
        rm[tid] = m;
        rs[tid] = logf(s);
    }
    __syncthreads();

    int row = m0 + r;
    if (row < N_NODES) {
        float sub = rm[r] + rs[r];
        out[row * NCLS + g * 4 + 0] = lg[r][g * 4 + 0] - sub;
        out[row * NCLS + g * 4 + 1] = lg[r][g * 4 + 1] - sub;
        out[row * NCLS + g * 4 + 2] = lg[r][g * 4 + 2] - sub;
        out[row * NCLS + g * 4 + 3] = lg[r][g * 4 + 3] - sub;
    }
}

// ---------------- launch ----------------
extern "C" void kernel_launch(void* const* d_in, const int* in_sizes, int n_in,
                              void* d_out, int out_size) {
    const float* features = (const float*)d_in[0];
    const int*   src      = (const int*)d_in[1];
    const int*   dst      = (const int*)d_in[2];
    const float* W1       = (const float*)d_in[3];
    const float* b1       = (const float*)d_in[4];
    const float* W2       = (const float*)d_in[5];
    const float* b2       = (const float*)d_in[6];
    float*       out      = (float*)d_out;

    const int NB  = (N_NODES + 255) / 256;      // 196
    const int EB  = (N_EDGES + 255) / 256;      // 3125
    const int IB  = (N_NODES * F4 + 255) / 256; // 6250
    const int PB  = (N_NODES + 7) / 8;          // 6250

    zero_deg_kernel<<<NB, 256>>>();
    deg_kernel<<<EB, 256>>>(dst);
    norm_kernel<<<NB, 256>>>();
    scan1_kernel<<<SCAN_BLOCKS, 256>>>();
    scan2_kernel<<<1, 256>>>();
    scan3_kernel<<<SCAN_BLOCKS, 256>>>();
    fill_kernel<<<EB, 256>>>(src, dst);
    init_kernel<<<IB, 256>>>((const float4*)features);

    prop_kernel<<<PB, 256>>>(0);   // x0 -> x1
    prop_kernel<<<PB, 256>>>(1);   // x1 -> x0
    prop_kernel<<<PB, 256>>>(0);   // x0 -> x1

    dim3 g1((N_NODES + 127) / 128, HID / 64);   // (391, 4)
    gemm1_kernel<<<g1, 256>>>(W1, b1);

    const int G2B = (N_NODES + 31) / 32;        // 1563
    gemm2_kernel<<<G2B, 320>>>(W2, b2, out);
}